// round 17
// baseline (speedup 1.0000x reference)
#include <cuda_runtime.h>
#include <cuda_fp16.h>
#include <math.h>
#include <stdint.h>

#define HD    1024
#define NL4   4
#define SEQ   512
#define NRW   64
#define LO    256
#define LDC   512
#define NPAIR (NRW*3)
#define MR    (NRW*LO)
#define NEGV  -1e30f

// ---------------------------------------------------------------------------
// Static device scratch
// ---------------------------------------------------------------------------
__device__ float  g_opt_enc[MR*HD];
__device__ int    g_opt_mask[MR];
__device__ float  g_doc_enc[NRW*LDC*HD];
__device__ int    g_doc_mask[NRW*LDC];
__device__ float  g_logitOpt[NPAIR*LO*LO];
__device__ float  g_attnOpt[NPAIR*LO*HD];
__device__ __half g_Xh[MR*7*HD];          // FC input, single rn fp16 plane
__device__ __half g_Wh[16*HD*HD];         // fp16 weights: comp|gate|attn|self
__device__ float  g_corr[MR*HD];
__device__ float  g_option[MR*HD];
__device__ float  g_logitD[NRW*LO*LDC];
__device__ float  g_kq[NRW*LO*LDC];
__device__ float  g_attnD[MR*HD];
__device__ float  g_cow[NRW*LO*LO];
__device__ float  g_coattn[MR*HD];
__device__ float  g_fusion[MR*HD];
__device__ float  g_logitS[NRW*LO*LO];
__device__ float  g_attn2[MR*HD];
__device__ float  g_fusion2[MR*HD];
__device__ float  g_rowq[MR];
__device__ float  g_rowk[MR];
__device__ float  g_rowkd[NRW*LDC];

// ---------------------------------------------------------------------------
// Helpers
// ---------------------------------------------------------------------------
__device__ __forceinline__ int read_fp(const int* __restrict__ p, int n)
{
    return (p[1] == 0) ? p[2*n] : p[n];   // int64 vs int32 sniff (values 300..450)
}

__device__ __forceinline__ void mma_f16(float* c, const uint32_t* a, const uint32_t* b)
{
    asm volatile(
        "mma.sync.aligned.m16n8k16.row.col.f32.f16.f16.f32 "
        "{%0,%1,%2,%3}, {%4,%5,%6,%7}, {%8,%9}, {%0,%1,%2,%3};"
        : "+f"(c[0]), "+f"(c[1]), "+f"(c[2]), "+f"(c[3])
        : "r"(a[0]), "r"(a[1]), "r"(a[2]), "r"(a[3]), "r"(b[0]), "r"(b[1]));
}

// ---------------------------------------------------------------------------
// Build kernels
// ---------------------------------------------------------------------------
__global__ void k_build_opt(const float* __restrict__ ll, const int* __restrict__ am,
                            const int* __restrict__ fpw)
{
    int o = blockIdx.x, n = blockIdx.y, t = threadIdx.x;
    int fp = read_fp(fpw, n);
    int idx = fp + o;
    int valid = (idx >= 0) && (idx < SEQ);
    int idxc = valid ? idx : (SEQ - 1);
    int m = valid && (am[n*SEQ + idxc] > 0);
    const float4* src = (const float4*)(ll + (size_t)(n*SEQ + idxc) * HD);
    float4* dst = (float4*)(g_opt_enc + (size_t)(n*LO + o) * HD);
    float4 v = m ? src[t] : make_float4(0.f,0.f,0.f,0.f);
    dst[t] = v;
    if (t == 0) g_opt_mask[n*LO + o] = m;
}

__global__ void k_build_doc(const float* __restrict__ ll, const int* __restrict__ am,
                            const int* __restrict__ fpw)
{
    int t0 = blockIdx.x, n = blockIdx.y, t = threadIdx.x;
    int fp = read_fp(fpw, n);
    int m = (t0 < fp) && (am[n*SEQ + t0] > 0);
    const float4* src = (const float4*)(ll + (size_t)(n*SEQ + t0) * HD);
    float4* dst = (float4*)(g_doc_enc + (size_t)(n*LDC + t0) * HD);
    float4 v = m ? src[t] : make_float4(0.f,0.f,0.f,0.f);
    dst[t] = v;
    if (t == 0) g_doc_mask[n*LDC + t0] = m;
}

__global__ void k_rowdot(const float* __restrict__ X, const float* __restrict__ w,
                         float* __restrict__ out)
{
    int r = blockIdx.x;
    const float* x = X + (size_t)r * HD;
    float s = 0.f;
    for (int i = threadIdx.x; i < HD; i += 256) s += x[i] * w[i];
    __shared__ float sh[256];
    sh[threadIdx.x] = s; __syncthreads();
    for (int st = 128; st > 0; st >>= 1) {
        if (threadIdx.x < st) sh[threadIdx.x] += sh[threadIdx.x + st];
        __syncthreads();
    }
    if (threadIdx.x == 0) out[r] = sh[0];
}

// weight fp32 -> fp16 (rn), elementwise
__global__ void k_cvtw(const float* __restrict__ w, __half* __restrict__ o)
{
    int i = blockIdx.x * 256 + threadIdx.x;
    float4 v = ((const float4*)w)[i];
    ((__half2*)o)[2*i]   = __floats2half2_rn(v.x, v.y);
    ((__half2*)o)[2*i+1] = __floats2half2_rn(v.z, v.w);
}

// ---------------------------------------------------------------------------
// fp32 SGEMMs (attention path) — unchanged
// ---------------------------------------------------------------------------
template<int EPI>   // 0=none 4=trilinear logits
__global__ __launch_bounds__(256) void k_gemm_nt(
    const float* __restrict__ A, const float* __restrict__ B, float* __restrict__ C,
    int M, int N, int K,
    long sA, long sB, long sC,
    const float* __restrict__ colScale,
    const float* __restrict__ ql, const float* __restrict__ kl,
    const int* __restrict__ mq, const int* __restrict__ mk,
    long sQl, long sKl,
    int pairMode)
{
    __shared__ float As[8][128];
    __shared__ float Bs[8][128];
    const int z = blockIdx.z;
    long offA, offB, offC, offQl, offKl;
    if (pairMode) {
        int n = z / 3, jj = z % 3;
        int b = n / NL4, i = n % NL4;
        int j = jj + (jj >= i ? 1 : 0);
        int mb = b * NL4 + j;
        offA = (long)n * LO * HD; offB = (long)mb * LO * HD;
        offC = (long)z * M * N;
        offQl = (long)n * LO; offKl = (long)mb * LO;
    } else {
        offA = z * sA; offB = z * sB; offC = z * sC;
        offQl = z * sQl; offKl = z * sKl;
    }
    const float* Ab = A + offA;
    const float* Bb = B + offB;
    const int tid = threadIdx.x;
    const int bm = blockIdx.y * 128, bn = blockIdx.x * 128;
    const int lr = tid >> 1, lc = (tid & 1) * 4;
    const int ty = tid >> 4, tx = tid & 15;
    float acc[8][8];
#pragma unroll
    for (int i = 0; i < 8; i++)
#pragma unroll
        for (int j = 0; j < 8; j++) acc[i][j] = 0.f;

    for (int k0 = 0; k0 < K; k0 += 8) {
        float4 av = *(const float4*)(Ab + (size_t)(bm + lr) * K + k0 + lc);
        float4 bv = *(const float4*)(Bb + (size_t)(bn + lr) * K + k0 + lc);
        if (EPI == 4) {
            bv.x *= colScale[k0 + lc];     bv.y *= colScale[k0 + lc + 1];
            bv.z *= colScale[k0 + lc + 2]; bv.w *= colScale[k0 + lc + 3];
        }
        As[lc][lr] = av.x; As[lc+1][lr] = av.y; As[lc+2][lr] = av.z; As[lc+3][lr] = av.w;
        Bs[lc][lr] = bv.x; Bs[lc+1][lr] = bv.y; Bs[lc+2][lr] = bv.z; Bs[lc+3][lr] = bv.w;
        __syncthreads();
#pragma unroll
        for (int kk = 0; kk < 8; kk++) {
            float a[8], b[8];
#pragma unroll
            for (int u = 0; u < 8; u++) { a[u] = As[kk][ty*8+u]; b[u] = Bs[kk][tx*8+u]; }
#pragma unroll
            for (int i = 0; i < 8; i++)
#pragma unroll
                for (int j = 0; j < 8; j++) acc[i][j] += a[i] * b[j];
        }
        __syncthreads();
    }
#pragma unroll
    for (int i = 0; i < 8; i++) {
        int m = bm + ty * 8 + i;
#pragma unroll
        for (int j = 0; j < 8; j++) {
            int nn = bn + tx * 8 + j;
            size_t ci = (size_t)offC + (size_t)m * N + nn;
            float v = acc[i][j];
            if (EPI == 0) C[ci] = v;
            else {
                v += ql[offQl + m] + kl[offKl + nn];
                C[ci] = (mq[offQl + m] && mk[offKl + nn]) ? v : NEGV;
            }
        }
    }
}

__global__ __launch_bounds__(256) void k_gemm_nn(
    const float* __restrict__ A, const float* __restrict__ B, float* __restrict__ C,
    int M, int N, int K, long sA, long sB, long sC, int pairMode)
{
    __shared__ float As[8][128];
    __shared__ float Bs[8][128];
    int z = blockIdx.z;
    long offA, offB, offC;
    if (pairMode) {
        int n = z / 3, jj = z % 3;
        int b = n / NL4, i = n % NL4;
        int j = jj + (jj >= i ? 1 : 0);
        int mb = b * NL4 + j;
        offA = (long)z * LO * LO; offB = (long)mb * LO * HD; offC = (long)z * LO * HD;
    } else { offA = z * sA; offB = z * sB; offC = z * sC; }
    const float* Ab = A + offA;
    const float* Bb = B + offB;
    int tid = threadIdx.x;
    int bm = blockIdx.y * 128, bn = blockIdx.x * 128;
    int lr = tid >> 1, lc = (tid & 1) * 4;
    int br = tid >> 5, bc = (tid & 31) * 4;
    int ty = tid >> 4, tx = tid & 15;
    float acc[8][8];
#pragma unroll
    for (int i = 0; i < 8; i++)
#pragma unroll
        for (int j = 0; j < 8; j++) acc[i][j] = 0.f;

    for (int k0 = 0; k0 < K; k0 += 8) {
        float4 av = *(const float4*)(Ab + (size_t)(bm + lr) * K + k0 + lc);
        As[lc][lr] = av.x; As[lc+1][lr] = av.y; As[lc+2][lr] = av.z; As[lc+3][lr] = av.w;
        float4 bv = *(const float4*)(Bb + (size_t)(k0 + br) * N + bn + bc);
        *(float4*)&Bs[br][bc] = bv;
        __syncthreads();
#pragma unroll
        for (int kk = 0; kk < 8; kk++) {
            float a[8], b[8];
#pragma unroll
            for (int u = 0; u < 8; u++) { a[u] = As[kk][ty*8+u]; b[u] = Bs[kk][tx*8+u]; }
#pragma unroll
            for (int i = 0; i < 8; i++)
#pragma unroll
                for (int j = 0; j < 8; j++) acc[i][j] += a[i] * b[j];
        }
        __syncthreads();
    }
#pragma unroll
    for (int i = 0; i < 8; i++) {
        int m = bm + ty * 8 + i;
#pragma unroll
        for (int j = 0; j < 8; j++) {
            int nn = bn + tx * 8 + j;
            C[(size_t)offC + (size_t)m * N + nn] = acc[i][j];
        }
    }
}

// ---------------------------------------------------------------------------
// Single-pass FP16 mma.sync FC GEMM: C[MR,HD] = act(Xh @ Wh^T + bias)
// Tile 128(M) x 256(N) x 16(K), 512 threads, 16 warps (2m x 8n, 64x32 each),
// 1 CTA/SM (regs), one barrier per chunk. Same warp tile + accumulation
// order as the 7820us version -> bit-identical numerics.
// A plane stride 544 (136w = 8 mod 32), B plane stride 1056 (264w = 8 mod 32):
// both give conflict-free (8t+g) LDS banks; producer STS row-per-thread.
// EPI: 1=tanh(+bias) 2=relu(+bias) 3=sigmoid gate: C = E1*g + E2*(1-g)
// ---------------------------------------------------------------------------
#define PT      544                 // A k-pair plane row stride (bytes)
#define PLANE_A (8*PT)              // 4352 B (8 k-pairs x 128 rows x half2)
#define PTB     1056                // B k-pair plane row stride (bytes)
#define PLANE_B (8*PTB)             // 8448 B (8 k-pairs x 256 rows x half2)
#define BUFB    (PLANE_A + PLANE_B) // 12800 B

template<int EPI>
__global__ __launch_bounds__(512, 1) void k_fc_mma(
    const __half* __restrict__ Ah_g, const __half* __restrict__ Bw,
    float* __restrict__ C, int K,
    const float* __restrict__ bias,
    const float* __restrict__ E1, const float* __restrict__ E2)
{
    __shared__ __align__(16) char sm[2*BUFB];   // 25600 B
    const int tid = threadIdx.x;
    const int lane = tid & 31, wid = tid >> 5;
    const int wm = wid & 1, wn = wid >> 1;      // 2 x 8 warp grid
    const int g = lane >> 2, t = lane & 3;
    const int bm = blockIdx.y << 7, bn = blockIdx.x << 8;

    float acc[4][4][4];
#pragma unroll
    for (int i = 0; i < 4; i++)
#pragma unroll
        for (int q = 0; q < 4; q++)
#pragma unroll
            for (int c = 0; c < 4; c++) acc[i][q][c] = 0.f;

    // Producer: t<128 -> A row t; 128<=t<384 -> B row t-128; rest idle.
    const bool isA = tid < 128;
    const bool isP = tid < 384;
    const int prow = isA ? tid : (tid - 128);
    const __half* srcH = isA ? (Ah_g + (size_t)(bm + prow) * K)
                             : (Bw   + (size_t)(bn + prow) * K);
    uint4 f0, f1;

    auto fetch = [&](int ch) {
        if (!isP) return;
        const __half* p = srcH + (ch << 4);
        f0 = *(const uint4*)p;
        f1 = *(const uint4*)(p + 8);
    };
    auto store_buf = [&](int buf) {
        if (!isP) return;
        char* d = sm + buf*BUFB + (isA ? 0 : PLANE_A) + prow*4;
        const int pt = isA ? PT : PTB;
        *(uint32_t*)(d + 0*pt) = f0.x; *(uint32_t*)(d + 1*pt) = f0.y;
        *(uint32_t*)(d + 2*pt) = f0.z; *(uint32_t*)(d + 3*pt) = f0.w;
        *(uint32_t*)(d + 4*pt) = f1.x; *(uint32_t*)(d + 5*pt) = f1.y;
        *(uint32_t*)(d + 6*pt) = f1.z; *(uint32_t*)(d + 7*pt) = f1.w;
    };

    const int T = K >> 4;
    fetch(0);
    store_buf(0);
    __syncthreads();

    for (int ch = 0; ch < T; ++ch) {
        const int buf = ch & 1;
        if (ch + 1 < T) fetch(ch + 1);

        const char* Ah = sm + buf*BUFB;
        const char* Bh = Ah + PLANE_A;
        const int rA = (wm << 6) + g;
        const int rB = (wn << 5) + g;

        uint32_t ah[4][4], bh[4][2];
#pragma unroll
        for (int i = 0; i < 4; i++) {
            const char* p = Ah + t*PT + (rA + (i << 4)) * 4;
            ah[i][0] = *(const uint32_t*)p;
            ah[i][1] = *(const uint32_t*)(p + 32);          // row + 8
            ah[i][2] = *(const uint32_t*)(p + 4*PT);        // k-pair t+4
            ah[i][3] = *(const uint32_t*)(p + 4*PT + 32);
        }
#pragma unroll
        for (int q = 0; q < 4; q++) {
            const char* p = Bh + t*PTB + (rB + (q << 3)) * 4;
            bh[q][0] = *(const uint32_t*)p;
            bh[q][1] = *(const uint32_t*)(p + 4*PTB);
        }
#pragma unroll
        for (int i = 0; i < 4; i++)
#pragma unroll
            for (int q = 0; q < 4; q++) mma_f16(acc[i][q], ah[i], bh[q]);

        // Producer store overlaps other warps' MMA; one barrier per chunk.
        if (ch + 1 < T) store_buf(buf ^ 1);
        __syncthreads();
    }

    // Epilogue
#pragma unroll
    for (int i = 0; i < 4; i++) {
        int row0 = bm + (wm << 6) + (i << 4) + g;
#pragma unroll
        for (int q = 0; q < 4; q++) {
            int col = bn + (wn << 5) + (q << 3) + (t << 1);
            float b0 = bias[col], b1 = bias[col + 1];
#pragma unroll
            for (int h = 0; h < 2; h++) {
                int row = row0 + h * 8;
                float v0 = acc[i][q][h*2+0] + b0;
                float v1 = acc[i][q][h*2+1] + b1;
                size_t ci = (size_t)row * HD + col;
                float2 o;
                if (EPI == 1)      { o.x = tanhf(v0);        o.y = tanhf(v1); }
                else if (EPI == 2) { o.x = fmaxf(v0, 0.f);   o.y = fmaxf(v1, 0.f); }
                else {
                    float g0 = 1.f / (1.f + expf(-v0));
                    float g1 = 1.f / (1.f + expf(-v1));
                    o.x = E1[ci]   * g0 + E2[ci]   * (1.f - g0);
                    o.y = E1[ci+1] * g1 + E2[ci+1] * (1.f - g1);
                }
                *(float2*)(C + ci) = o;
            }
        }
    }
}

// ---------------------------------------------------------------------------
// Softmax kernels
// ---------------------------------------------------------------------------
__global__ void k_row_softmax(float* __restrict__ X, int Cdim,
    const int* __restrict__ mqb, const int* __restrict__ mkb,
    long sX, long sMq, long sMk, int pairMode)
{
    int z = blockIdx.y, row = blockIdx.x;
    long offX, offMq, offMk;
    if (pairMode) {
        int n = z / 3, jj = z % 3;
        int b = n / NL4, i = n % NL4;
        int j = jj + (jj >= i ? 1 : 0);
        int mb = b * NL4 + j;
        offX = (long)z * LO * LO; offMq = (long)n * LO; offMk = (long)mb * LO;
    } else { offX = z * sX; offMq = z * sMq; offMk = z * sMk; }
    float* x = X + offX + (long)row * Cdim;
    const int* mk = mkb + offMk;
    int qm = mqb[offMq + row];
    int tid = threadIdx.x;
    __shared__ float sh[256];
    float mx = -3.4e38f;
    for (int c = tid; c < Cdim; c += 256) mx = fmaxf(mx, x[c]);
    sh[tid] = mx; __syncthreads();
    for (int s = 128; s > 0; s >>= 1) {
        if (tid < s) sh[tid] = fmaxf(sh[tid], sh[tid + s]);
        __syncthreads();
    }
    mx = sh[0]; __syncthreads();
    float sum = 0.f;
    for (int c = tid; c < Cdim; c += 256) sum += expf(x[c] - mx);
    sh[tid] = sum; __syncthreads();
    for (int s = 128; s > 0; s >>= 1) {
        if (tid < s) sh[tid] += sh[tid + s];
        __syncthreads();
    }
    float inv = 1.f / sh[0];
    for (int c = tid; c < Cdim; c += 256) {
        float e = expf(x[c] - mx);
        x[c] = (qm && mk[c]) ? e * inv : 0.f;
    }
}

__global__ void k_col_softmax()
{
    int n = blockIdx.y;
    int t = blockIdx.x * 256 + threadIdx.x;
    const float* x = g_logitD + (size_t)n * LO * LDC;
    float mx = -3.4e38f;
    for (int o = 0; o < LO; o++) mx = fmaxf(mx, x[(size_t)o * LDC + t]);
    float sum = 0.f;
    for (int o = 0; o < LO; o++) sum += expf(x[(size_t)o * LDC + t] - mx);
    float inv = 1.f / sum;
    int km = g_doc_mask[n*LDC + t];
    float* y = g_kq + (size_t)n * LO * LDC;
    for (int o = 0; o < LO; o++) {
        float e = expf(x[(size_t)o * LDC + t] - mx);
        y[(size_t)o * LDC + t] = (km && g_opt_mask[n*LO + o]) ? e * inv : 0.f;
    }
}

// ---------------------------------------------------------------------------
// Concat builders (emit single rn fp16 plane) + final max
// ---------------------------------------------------------------------------
__global__ void k_feats()
{
    size_t idx = (size_t)blockIdx.x * 256 + threadIdx.x;
    size_t r = idx >> 10;
    int h = (int)(idx & 1023);
    int n = (int)(r >> 8);
    int o = (int)(r & 255);
    float cur = g_opt_enc[idx];
    __half* xh = g_Xh + r * (7*HD);
    xh[h] = __float2half_rn(cur);
#pragma unroll
    for (int jj = 0; jj < 3; jj++) {
        float a = g_attnOpt[(((size_t)(n*3 + jj) * LO + o) << 10) + h];
        xh[(size_t)(1 + 2*jj)*HD + h] = __float2half_rn(cur * a);
        xh[(size_t)(2 + 2*jj)*HD + h] = __float2half_rn(cur - a);
    }
}

__global__ void k_concat2()
{
    size_t idx = (size_t)blockIdx.x * 256 + threadIdx.x;
    size_t r = idx >> 10;
    int h = (int)(idx & 1023);
    __half* xh = g_Xh + r * (2*HD);
    xh[h] = __float2half_rn(g_opt_enc[idx]);
    xh[(size_t)HD + h] = __float2half_rn(g_corr[idx]);
}

__global__ void k_concat3()
{
    size_t idx = (size_t)blockIdx.x * 256 + threadIdx.x;
    size_t r = idx >> 10;
    int h = (int)(idx & 1023);
    __half* xh = g_Xh + r * (3*HD);
    xh[h] = __float2half_rn(g_option[idx]);
    xh[(size_t)HD + h] = __float2half_rn(g_attnD[idx]);
    xh[(size_t)2*HD + h] = __float2half_rn(g_coattn[idx]);
}

__global__ void k_concat4()
{
    size_t idx = (size_t)blockIdx.x * 256 + threadIdx.x;
    size_t r = idx >> 10;
    int h = (int)(idx & 1023);
    float f = g_fusion[idx];
    float a = g_attn2[idx];
    __half* xh = g_Xh + r * (4*HD);
    xh[h] = __float2half_rn(f);
    xh[(size_t)HD + h] = __float2half_rn(a);
    xh[(size_t)2*HD + h] = __float2half_rn(f * a);
    xh[(size_t)3*HD + h] = __float2half_rn(f - a);
}

__global__ void k_final(float* __restrict__ out)
{
    int n = blockIdx.y;
    int h = blockIdx.x * 256 + threadIdx.x;
    float mx = NEGV;
    for (int o = 0; o < LO; o++) {
        if (g_opt_mask[n*LO + o])
            mx = fmaxf(mx, g_fusion2[((size_t)(n*LO + o) << 10) + h]);
    }
    out[(size_t)n * HD + h] = mx;
}

// ---------------------------------------------------------------------------
// Launch
// ---------------------------------------------------------------------------
extern "C" void kernel_launch(void* const* d_in, const int* in_sizes, int n_in,
                              void* d_out, int out_size)
{
    const float* ll  = (const float*)d_in[0];
    const int*   am  = (const int*)d_in[1];
    const int*   fpw = (const int*)d_in[2];
    int base = (in_sizes[3] <= 8) ? 4 : 3;
    const float* attn_w1   = (const float*)d_in[base+0];
    const float* attn_w2   = (const float*)d_in[base+1];
    const float* attn_w3   = (const float*)d_in[base+2];
    const float* opt_w1    = (const float*)d_in[base+3];
    const float* opt_w2    = (const float*)d_in[base+4];
    const float* opt_w3    = (const float*)d_in[base+5];
    const float* self_w1   = (const float*)d_in[base+6];
    const float* self_w2   = (const float*)d_in[base+7];
    const float* self_w3   = (const float*)d_in[base+8];
    const float* attn_fc_w = (const float*)d_in[base+9];
    const float* attn_fc_b = (const float*)d_in[base+10];
    const float* comp_fc_w = (const float*)d_in[base+11];
    const float* comp_fc_b = (const float*)d_in[base+12];
    const float* gate_fc_w = (const float*)d_in[base+13];
    const float* gate_fc_b = (const float*)d_in[base+14];
    const float* self_fc_w = (const float*)d_in[base+15];
    const float* self_fc_b = (const float*)d_in[base+16];
    float* out = (float*)d_out;

    float *opt_enc, *doc_enc, *logitOpt, *attnOpt, *corr, *option;
    float *logitD, *kq, *attnD, *cow, *coattn, *fusion, *logitS, *attn2, *fusion2;
    float *rowq, *rowk, *rowkd;
    __half *Xh, *Wh;
    int *opt_mask, *doc_mask;
    cudaGetSymbolAddress((void**)&opt_enc,  g_opt_enc);
    cudaGetSymbolAddress((void**)&doc_enc,  g_doc_enc);
    cudaGetSymbolAddress((void**)&logitOpt, g_logitOpt);
    cudaGetSymbolAddress((void**)&attnOpt,  g_attnOpt);
    cudaGetSymbolAddress((void**)&Xh,       g_Xh);
    cudaGetSymbolAddress((void**)&Wh,       g_Wh);
    cudaGetSymbolAddress((void**)&corr,     g_corr);
    cudaGetSymbolAddress((void**)&option,   g_option);
    cudaGetSymbolAddress((void**)&logitD,   g_logitD);
    cudaGetSymbolAddress((void**)&kq,       g_kq);
    cudaGetSymbolAddress((void**)&attnD,    g_attnD);
    cudaGetSymbolAddress((void**)&cow,      g_cow);
    cudaGetSymbolAddress((void**)&coattn,   g_coattn);
    cudaGetSymbolAddress((void**)&fusion,   g_fusion);
    cudaGetSymbolAddress((void**)&logitS,   g_logitS);
    cudaGetSymbolAddress((void**)&attn2,    g_attn2);
    cudaGetSymbolAddress((void**)&fusion2,  g_fusion2);
    cudaGetSymbolAddress((void**)&rowq,     g_rowq);
    cudaGetSymbolAddress((void**)&rowk,     g_rowk);
    cudaGetSymbolAddress((void**)&rowkd,    g_rowkd);
    cudaGetSymbolAddress((void**)&opt_mask, g_opt_mask);
    cudaGetSymbolAddress((void**)&doc_mask, g_doc_mask);

    __half* Wcomp = Wh;
    __half* Wgate = Wh + (size_t)7*HD*HD;
    __half* Wattn = Wh + (size_t)9*HD*HD;
    __half* Wself = Wh + (size_t)12*HD*HD;

    const int EW_BLOCKS = (MR * HD) / 256;   // 65536
    const dim3 FC_GRID(HD/256, MR/128);      // 4 x 128 = 512 blocks

    // 0) convert FC weights to fp16 once
    k_cvtw<<<(7*HD*HD/4)/256, 256>>>(comp_fc_w, Wcomp);
    k_cvtw<<<(2*HD*HD/4)/256, 256>>>(gate_fc_w, Wgate);
    k_cvtw<<<(3*HD*HD/4)/256, 256>>>(attn_fc_w, Wattn);
    k_cvtw<<<(4*HD*HD/4)/256, 256>>>(self_fc_w, Wself);

    // 1) build encodings + masks
    k_build_opt<<<dim3(LO,  NRW), 256>>>(ll, am, fpw);
    k_build_doc<<<dim3(LDC, NRW), 256>>>(ll, am, fpw);

    // 2) opt-opt cross attention (192 pairs)
    k_rowdot<<<MR, 256>>>(opt_enc, opt_w1, rowq);
    k_rowdot<<<MR, 256>>>(opt_enc, opt_w2, rowk);
    k_gemm_nt<4><<<dim3(LO/128, LO/128, NPAIR), 256>>>(
        opt_enc, opt_enc, logitOpt, LO, LO, HD, 0,0,0,
        opt_w3, rowq, rowk, opt_mask, opt_mask, 0,0, 1);
    k_row_softmax<<<dim3(LO, NPAIR), 256>>>(logitOpt, LO, opt_mask, opt_mask, 0,0,0, 1);
    k_gemm_nn<<<dim3(HD/128, LO/128, NPAIR), 256>>>(
        logitOpt, opt_enc, attnOpt, LO, HD, LO, 0,0,0, 1);

    // 3) comp FC (K = 7H), single-pass fp16
    k_feats<<<EW_BLOCKS, 256>>>();
    k_fc_mma<1><<<FC_GRID, 512>>>(Xh, Wcomp, corr, 7*HD, comp_fc_b, nullptr, nullptr);

    // 4) gate FC (K = 2H) with fused gate-combine -> option
    k_concat2<<<EW_BLOCKS, 256>>>();
    k_fc_mma<3><<<FC_GRID, 512>>>(Xh, Wgate, option, 2*HD, gate_fc_b, opt_enc, corr);

    // 5) doc attention (with co-attention)
    k_rowdot<<<MR, 256>>>(option, attn_w1, rowq);
    k_rowdot<<<NRW*LDC, 256>>>(doc_enc, attn_w2, rowkd);
    k_gemm_nt<4><<<dim3(LDC/128, LO/128, NRW), 256>>>(
        option, doc_enc, logitD, LO, LDC, HD,
        (long)LO*HD, (long)LDC*HD, (long)LO*LDC,
        attn_w3, rowq, rowkd, opt_mask, doc_mask, LO, LDC, 0);
    k_col_softmax<<<dim3(LDC/256, NRW), 256>>>();
    k_row_softmax<<<dim3(LO, NRW), 256>>>(logitD, LDC, opt_mask, doc_mask,
        (long)LO*LDC, LO, LDC, 0);
    k_gemm_nn<<<dim3(HD/128, LO/128, NRW), 256>>>(
        logitD, doc_enc, attnD, LO, HD, LDC,
        (long)LO*LDC, (long)LDC*HD, (long)LO*HD, 0);
    k_gemm_nt<0><<<dim3(LO/128, LO/128, NRW), 256>>>(
        logitD, kq, cow, LO, LO, LDC,
        (long)LO*LDC, (long)LO*LDC, (long)LO*LO,
        nullptr, nullptr, nullptr, nullptr, nullptr, 0,0, 0);
    k_gemm_nn<<<dim3(HD/128, LO/128, NRW), 256>>>(
        cow, option, coattn, LO, HD, LO,
        (long)LO*LO, (long)LO*HD, (long)LO*HD, 0);

    // 6) attn FC (K = 3H) -> fusion
    k_concat3<<<EW_BLOCKS, 256>>>();
    k_fc_mma<1><<<FC_GRID, 512>>>(Xh, Wattn, fusion, 3*HD, attn_fc_b, nullptr, nullptr);

    // 7) self attention
    k_rowdot<<<MR, 256>>>(fusion, self_w1, rowq);
    k_rowdot<<<MR, 256>>>(fusion, self_w2, rowk);
    k_gemm_nt<4><<<dim3(LO/128, LO/128, NRW), 256>>>(
        fusion, fusion, logitS, LO, LO, HD,
        (long)LO*HD, (long)LO*HD, (long)LO*LO,
        self_w3, rowq, rowk, opt_mask, opt_mask, LO, LO, 0);
    k_row_softmax<<<dim3(LO, NRW), 256>>>(logitS, LO, opt_mask, opt_mask,
        (long)LO*LO, LO, LO, 0);
    k_gemm_nn<<<dim3(HD/128, LO/128, NRW), 256>>>(
        logitS, fusion, attn2, LO, HD, LO,
        (long)LO*LO, (long)LO*HD, (long)LO*HD, 0);

    // 8) self FC (K = 4H) -> fusion2
    k_concat4<<<EW_BLOCKS, 256>>>();
    k_fc_mma<2><<<FC_GRID, 512>>>(Xh, Wself, fusion2, 4*HD, self_fc_b, nullptr, nullptr);

    // 9) masked max over option positions
    k_final<<<dim3(HD/256, NRW), 256>>>(out);
}